// round 16
// baseline (speedup 1.0000x reference)
#include <cuda_runtime.h>
#include <cuda_fp16.h>
#include <cstdint>
#include <cstddef>

#define NM 50000
#define EM 800000
#define D0 64
#define D1 128
#define D2 256
#define ODIM 128
#define NB ((NM + 1023) / 1024)

// ---------------- device scratch ------------------------------------------
__device__ __half g_feath[(size_t)NM * D0];   // 6.4 MB  fp16 features
__device__ __half g_h1h[(size_t)NM * D1];     // 12.8 MB fp16
__device__ __half g_h2h[(size_t)NM * D2];     // 25.6 MB fp16 (GEMM A)
__device__ __half g_Ph[(size_t)NM * D2];      // 25.6 MB fp16 (Pin 0-127, Pout 128-255)
__device__ uint32_t g_Wt2h[(D2 / 2) * D2];    // [k2][n] half2-packed weights (B)
__device__ int    g_src[EM];
__device__ int    g_dst[EM];
__device__ int    g_adj[2][EM];
__device__ int    g_cnt[2][NM];
__device__ int    g_rowptr[2][NM];
__device__ int    g_cursor[2][NM];
__device__ float  g_inv[2][NM];
__device__ int    g_part[2][64];
__device__ int    g_ready[2][64];             // publish flags for fused scan
__device__ int    g_flag32;                   // static-init 0; reset by scan each pass

// ------ setup: zero counts + feature->fp16 + int32/int64 detection --------
__global__ void initA_kernel(const float* __restrict__ feat,
                             const unsigned* __restrict__ edges32,
                             int n, int nfeat2, int E) {
    int i = blockIdx.x * blockDim.x + threadIdx.x;
    if (i < n) { g_cnt[0][i] = 0; g_cnt[1][i] = 0; }
    if (i < nfeat2) {
        float2 f = ((const float2*)feat)[i];
        ((__half2*)g_feath)[i] = __floats2half2_rn(f.x, f.y);
    }
    // detection: if edges are int64 (values < 50000) every odd word is 0.
    unsigned hiw = (i < E) ? edges32[2 * i + 1] : 0u;
    if (__any_sync(__activemask(), hiw != 0u) && (threadIdx.x & 31) == 0 && hiw != 0u)
        g_flag32 = 1;   // benign race: all writers store 1
}

// convert + count, 4 edges/thread, NO-RETURN atomics (REDG); resets scan flags.
__global__ void convert_count_kernel(const void* __restrict__ e, int E) {
    int gt = blockIdx.x * blockDim.x + threadIdx.x;
    if (gt < 128) ((int*)g_ready)[gt] = 0;
    int base = gt * 4;
    if (base >= E) return;
    int cnt = min(4, E - base);
    int s[4], d[4];
    if (g_flag32) {
        const int* p = (const int*)e;
        for (int j = 0; j < cnt; j++) { s[j] = p[base + j]; d[j] = p[E + base + j]; }
    } else {
        const long long* p = (const long long*)e;
        for (int j = 0; j < cnt; j++) { s[j] = (int)p[base + j]; d[j] = (int)p[E + base + j]; }
    }
    for (int j = 0; j < cnt; j++) { g_src[base + j] = s[j]; g_dst[base + j] = d[j]; }
    for (int j = 0; j < cnt; j++) atomicAdd(&g_cnt[0][d[j]], 1);
    for (int j = 0; j < cnt; j++) atomicAdd(&g_cnt[1][s[j]], 1);
}

// ---- fused single-pass scan: block scan + cross-block spin-prefix --------
// Grid (NB, 2) = 98 blocks of 1024 <= 148 SMs -> co-resident wave 1.
__global__ void scan_fused_kernel(const float* __restrict__ W, int n) {
    int flat = (blockIdx.y * NB + blockIdx.x) * 1024 + threadIdx.x;
    if (flat < (D2 / 2) * D2) {
        int k2 = flat / D2, j = flat % D2;
        int base = (j < ODIM) ? j * 512 + 2 * k2 : (j - ODIM) * 512 + 256 + 2 * k2;
        __half2 h = __floats2half2_rn(W[base], W[base + 1]);
        g_Wt2h[flat] = *(uint32_t*)&h;
    }
    if (flat == 0) g_flag32 = 0;      // reset for next replay

    int dir = blockIdx.y;
    int tid = threadIdx.x;
    int i = blockIdx.x * 1024 + tid;
    int v = (i < n) ? g_cnt[dir][i] : 0;
    int lane = tid & 31, w = tid >> 5;
    int x = v;
    #pragma unroll
    for (int o = 1; o < 32; o <<= 1) {
        int y = __shfl_up_sync(0xffffffffu, x, o);
        if (lane >= o) x += y;
    }
    __shared__ int ws[32];
    __shared__ int base_s;
    if (lane == 31) ws[w] = x;
    __syncthreads();
    if (w == 0) {
        int y = ws[lane];
        #pragma unroll
        for (int o = 1; o < 32; o <<= 1) {
            int z = __shfl_up_sync(0xffffffffu, y, o);
            if (lane >= o) y += z;
        }
        ws[lane] = y;
    }
    __syncthreads();
    int excl = x - v + (w ? ws[w - 1] : 0);

    if (tid == 0) {
        g_part[dir][blockIdx.x] = ws[31];
        __threadfence();
        atomicExch(&g_ready[dir][blockIdx.x], 1);
    }
    if (w == 0) {
        int acc = 0;
        for (int b = lane; b < (int)blockIdx.x; b += 32) {
            while (atomicAdd(&g_ready[dir][b], 0) == 0) { }
            acc += g_part[dir][b];
        }
        #pragma unroll
        for (int o = 16; o; o >>= 1) acc += __shfl_down_sync(0xffffffffu, acc, o);
        if (lane == 0) base_s = acc;
    }
    __syncthreads();
    if (i < n) {
        int r = excl + base_s;
        g_rowptr[dir][i] = r;
        g_cursor[dir][i] = r;
        g_inv[dir][i] = 1.0f / fmaxf((float)v, 1.0f);
    }
}

// ---- fill: 1 edge/thread, return-atomic cursor (measured-best variant) ---
__global__ void fill_kernel(int E) {
    int i = blockIdx.x * blockDim.x + threadIdx.x;
    if (i >= E) return;
    int s = g_src[i], d = g_dst[i];
    int p = atomicAdd(&g_cursor[0][d], 1);
    g_adj[0][p] = s;
    int q = atomicAdd(&g_cursor[1][s], 1);
    g_adj[1][q] = d;
}

// ---------------- hop1: feat fp16 (D=64) -> h1 fp16 [N,128] ---------------
// Masked full-width batches: no serial remainder loop.
__global__ void __launch_bounds__(256) hop1_kernel(__half* __restrict__ h1, int n) {
    int gid = blockIdx.x * blockDim.x + threadIdx.x;
    int node = gid >> 4;
    int lane = gid & 15;
    int dir = blockIdx.y;
    if (node >= n) return;
    int start = g_rowptr[dir][node];
    int deg   = g_cnt[dir][node];
    const int* adj = g_adj[dir] + start;
    float acc[4] = {};
    const uint2 zero2 = make_uint2(0u, 0u);
    for (int t = 0; t < deg; t += 8) {
        int rem = deg - t;                     // >= 1
        int u[8];
        #pragma unroll
        for (int j = 0; j < 8; j++) u[j] = __ldg(&adj[t + min(j, rem - 1)]);
        uint2 rs[8];
        #pragma unroll
        for (int j = 0; j < 8; j++)
            rs[j] = __ldg((const uint2*)(g_feath + (size_t)u[j] * D0) + lane);
        #pragma unroll
        for (int j = 0; j < 8; j++)
            if (j >= rem) rs[j] = zero2;       // mask invalid lanes (exact)
        #pragma unroll
        for (int p = 0; p < 4; p++) {
            const __half2* a = (const __half2*)&rs[2 * p];
            const __half2* b = (const __half2*)&rs[2 * p + 1];
            __half2 s0 = __hadd2(a[0], b[0]);
            __half2 s1 = __hadd2(a[1], b[1]);
            float2 f0 = __half22float2(s0);
            float2 f1 = __half22float2(s1);
            acc[0] += f0.x; acc[1] += f0.y; acc[2] += f1.x; acc[3] += f1.y;
        }
    }
    float w = g_inv[dir][node];
    __half2* out = (__half2*)(h1 + (size_t)node * D1 + dir * D0 + lane * 4);
    out[0] = __floats2half2_rn(acc[0] * w, acc[1] * w);
    out[1] = __floats2half2_rn(acc[2] * w, acc[3] * w);
}

// ---------------- hop2: h1 fp16 (D=128) -> h2 fp16 [N,256] ----------------
__global__ void __launch_bounds__(256) hop2_kernel(
    const __half* __restrict__ h1, __half* __restrict__ h2, int n)
{
    int gid = blockIdx.x * blockDim.x + threadIdx.x;
    int node = gid >> 4;
    int lane = gid & 15;
    int dir = blockIdx.y;
    if (node >= n) return;
    int start = g_rowptr[dir][node];
    int deg   = g_cnt[dir][node];
    const int* adj = g_adj[dir] + start;
    float acc[8] = {};
    const uint4 zero4 = make_uint4(0u, 0u, 0u, 0u);
    for (int t = 0; t < deg; t += 8) {
        int rem = deg - t;
        int u[8];
        #pragma unroll
        for (int j = 0; j < 8; j++) u[j] = __ldg(&adj[t + min(j, rem - 1)]);
        uint4 rs[8];
        #pragma unroll
        for (int j = 0; j < 8; j++)
            rs[j] = __ldg((const uint4*)(h1 + (size_t)u[j] * D1) + lane);
        #pragma unroll
        for (int j = 0; j < 8; j++)
            if (j >= rem) rs[j] = zero4;
        #pragma unroll
        for (int p = 0; p < 4; p++) {
            const __half2* a = (const __half2*)&rs[2 * p];
            const __half2* b = (const __half2*)&rs[2 * p + 1];
            #pragma unroll
            for (int j = 0; j < 4; j++) {
                __half2 s = __hadd2(a[j], b[j]);
                float2 f = __half22float2(s);
                acc[2 * j]     += f.x;
                acc[2 * j + 1] += f.y;
            }
        }
    }
    float w = g_inv[dir][node];
    __half2 o[4];
    #pragma unroll
    for (int j = 0; j < 4; j++)
        o[j] = __floats2half2_rn(acc[2 * j] * w, acc[2 * j + 1] * w);
    *(uint4*)(h2 + (size_t)node * D2 + dir * D1 + lane * 8) = *(uint4*)o;
}

// ---------------- fp16 GEMM, double-buffered smem (1 sync / k-tile) -------
__device__ __forceinline__ void mma_f16(float* c, const uint32_t* a,
                                        uint32_t b0, uint32_t b1) {
    asm volatile(
        "mma.sync.aligned.m16n8k16.row.col.f32.f16.f16.f32 "
        "{%0,%1,%2,%3}, {%4,%5,%6,%7}, {%8,%9}, {%0,%1,%2,%3};"
        : "+f"(c[0]), "+f"(c[1]), "+f"(c[2]), "+f"(c[3])
        : "r"(a[0]), "r"(a[1]), "r"(a[2]), "r"(a[3]), "r"(b0), "r"(b1));
}

__global__ void __launch_bounds__(256, 2) gemm_f16_kernel(
    const __half* __restrict__ A, __half* __restrict__ C, int N)
{
    __shared__ uint32_t As[2][128][20];
    __shared__ uint32_t Bs[2][16][136];
    int tid = threadIdx.x;
    int warp = tid >> 5, lane = tid & 31;
    int warpRow = warp >> 1;
    int warpCol = warp & 1;
    int g = lane >> 2, q = lane & 3;
    int blockRow = blockIdx.x * 128;
    int blockCol = blockIdx.y * 128;
    float c[2][8][4] = {};

    int arow = tid >> 2;
    int ac4  = tid & 3;
    int bk2  = tid >> 5;
    int bn4  = tid & 31;

    const uint4* Ag = (const uint4*)A;
    const uint4* Bg = (const uint4*)g_Wt2h;
    uint4 bufA[2], bufB[2];
    const uint4 zero4 = make_uint4(0u, 0u, 0u, 0u);

    #pragma unroll
    for (int i = 0; i < 2; i++) {
        int row = blockRow + arow + i * 64;
        bufA[i] = (row < N) ? __ldg(Ag + (size_t)row * 32 + ac4) : zero4;
        bufB[i] = __ldg(Bg + (size_t)(bk2 + i * 8) * 64 + (blockCol >> 2) + bn4);
    }
    #pragma unroll
    for (int i = 0; i < 2; i++) {
        *(uint4*)&As[0][arow + i * 64][ac4 * 4] = bufA[i];
        *(uint4*)&Bs[0][bk2 + i * 8][bn4 * 4] = bufB[i];
    }
    __syncthreads();

    for (int kt = 0; kt < 8; kt++) {
        int cur = kt & 1;
        if (kt < 7) {
            #pragma unroll
            for (int i = 0; i < 2; i++) {
                int row = blockRow + arow + i * 64;
                bufA[i] = (row < N) ? __ldg(Ag + (size_t)row * 32 + (kt + 1) * 4 + ac4) : zero4;
                bufB[i] = __ldg(Bg + (size_t)((kt + 1) * 16 + bk2 + i * 8) * 64 + (blockCol >> 2) + bn4);
            }
        }
        #pragma unroll
        for (int ks = 0; ks < 2; ks++) {
            int kb = ks * 8;
            uint32_t a[2][4];
            #pragma unroll
            for (int mt = 0; mt < 2; mt++) {
                int rb = warpRow * 32 + mt * 16;
                a[mt][0] = As[cur][rb + g    ][kb + q    ];
                a[mt][1] = As[cur][rb + g + 8][kb + q    ];
                a[mt][2] = As[cur][rb + g    ][kb + q + 4];
                a[mt][3] = As[cur][rb + g + 8][kb + q + 4];
            }
            #pragma unroll
            for (int nt = 0; nt < 8; nt++) {
                int cb = warpCol * 64 + nt * 8 + g;
                uint32_t b0 = Bs[cur][kb + q    ][cb];
                uint32_t b1 = Bs[cur][kb + q + 4][cb];
                mma_f16(c[0][nt], a[0], b0, b1);
                mma_f16(c[1][nt], a[1], b0, b1);
            }
        }
        if (kt < 7) {
            #pragma unroll
            for (int i = 0; i < 2; i++) {
                *(uint4*)&As[1 - cur][arow + i * 64][ac4 * 4] = bufA[i];
                *(uint4*)&Bs[1 - cur][bk2 + i * 8][bn4 * 4] = bufB[i];
            }
            __syncthreads();
        }
    }

    #pragma unroll
    for (int mt = 0; mt < 2; mt++)
        #pragma unroll
        for (int nt = 0; nt < 8; nt++) {
            int col = blockCol + warpCol * 64 + nt * 8 + q * 2;
            int r0 = blockRow + warpRow * 32 + mt * 16 + g;
            if (r0 < N)
                *(__half2*)(C + (size_t)r0 * D2 + col) =
                    __floats2half2_rn(c[mt][nt][0], c[mt][nt][1]);
            int r1 = r0 + 8;
            if (r1 < N)
                *(__half2*)(C + (size_t)r1 * D2 + col) =
                    __floats2half2_rn(c[mt][nt][2], c[mt][nt][3]);
        }
}

// ---------------- fused hop3: aggregate P fp16, scale, bias ---------------
__global__ void __launch_bounds__(256) hop3_kernel(
    const __half* __restrict__ P, const float* __restrict__ bias,
    float* __restrict__ out, int n)
{
    int node = blockIdx.x * 8 + (threadIdx.x >> 5);
    int lane = threadIdx.x & 31;
    if (node >= n) return;
    float aI[4] = {}, aO[4] = {};
    const uint2 zero2 = make_uint2(0u, 0u);
    #pragma unroll
    for (int dir = 0; dir < 2; dir++) {
        float* acc = dir ? aO : aI;
        int off = dir ? ODIM : 0;
        int start = g_rowptr[dir][node];
        int deg   = g_cnt[dir][node];
        const int* adj = g_adj[dir] + start;
        for (int t = 0; t < deg; t += 8) {
            int rem = deg - t;
            int u[8];
            #pragma unroll
            for (int j = 0; j < 8; j++) u[j] = __ldg(&adj[t + min(j, rem - 1)]);
            uint2 rs[8];
            #pragma unroll
            for (int j = 0; j < 8; j++)
                rs[j] = __ldg((const uint2*)(P + (size_t)u[j] * D2 + off) + lane);
            #pragma unroll
            for (int j = 0; j < 8; j++)
                if (j >= rem) rs[j] = zero2;
            #pragma unroll
            for (int p = 0; p < 4; p++) {
                const __half2* a = (const __half2*)&rs[2 * p];
                const __half2* b = (const __half2*)&rs[2 * p + 1];
                __half2 s0 = __hadd2(a[0], b[0]);
                __half2 s1 = __hadd2(a[1], b[1]);
                float2 f0 = __half22float2(s0);
                float2 f1 = __half22float2(s1);
                acc[0] += f0.x; acc[1] += f0.y; acc[2] += f1.x; acc[3] += f1.y;
            }
        }
    }
    float wi = g_inv[0][node], wo = g_inv[1][node];
    float4 b = __ldg((const float4*)bias + lane);
    float4 r;
    r.x = aI[0] * wi + aO[0] * wo + b.x;
    r.y = aI[1] * wi + aO[1] * wo + b.y;
    r.z = aI[2] * wi + aO[2] * wo + b.z;
    r.w = aI[3] * wi + aO[3] * wo + b.w;
    ((float4*)(out + (size_t)node * ODIM))[lane] = r;
}

// ---------------- launch ----------------------------------------------------
extern "C" void kernel_launch(void* const* d_in, const int* in_sizes, int n_in,
                              void* d_out, int out_size)
{
    const float* feat  = (const float*)d_in[0];
    const void*  edges = d_in[1];
    const float* W     = (const float*)d_in[2];
    const float* bias  = (const float*)d_in[3];
    float* out = (float*)d_out;

    int N = in_sizes[0] / D0;     // 50000
    int E = in_sizes[1] / 2;      // 800000

    __half *h1, *h2, *P;
    cudaGetSymbolAddress((void**)&h1, g_h1h);
    cudaGetSymbolAddress((void**)&h2, g_h2h);
    cudaGetSymbolAddress((void**)&P,  g_Ph);

    const int T = 256;
    int nfeat2 = N * D0 / 2;
    initA_kernel<<<(nfeat2 + T - 1) / T, T>>>(feat, (const unsigned*)edges, N, nfeat2, E);
    {
        int threads = (E + 3) / 4;
        convert_count_kernel<<<(threads + T - 1) / T, T>>>(edges, E);
    }
    {
        dim3 sgrid(NB, 2);
        scan_fused_kernel<<<sgrid, 1024>>>(W, N);
    }
    fill_kernel<<<(E + T - 1) / T, T>>>(E);
    {
        unsigned total = (unsigned)N * 16;
        dim3 g((total + T - 1) / T, 2);
        hop1_kernel<<<g, T>>>(h1, N);
        hop2_kernel<<<g, T>>>(h1, h2, N);
    }
    {
        dim3 g((N + 127) / 128, 2);
        gemm_f16_kernel<<<g, T>>>(h2, P, N);
    }
    hop3_kernel<<<(N + 7) / 8, T>>>(P, bias, out, N);
}

// round 17
// speedup vs baseline: 1.1032x; 1.1032x over previous
#include <cuda_runtime.h>
#include <cuda_fp16.h>
#include <cstdint>
#include <cstddef>

#define NM 50000
#define EM 800000
#define D0 64
#define D1 128
#define D2 256
#define ODIM 128
#define NB ((NM + 1023) / 1024)

// ---------------- device scratch ------------------------------------------
__device__ __half g_feath[(size_t)NM * D0];   // 6.4 MB  fp16 features
__device__ __half g_h1h[(size_t)NM * D1];     // 12.8 MB fp16
__device__ __half g_h2h[(size_t)NM * D2];     // 25.6 MB fp16 (GEMM A)
__device__ __half g_Ph[(size_t)NM * D2];      // 25.6 MB fp16 (Pin 0-127, Pout 128-255)
__device__ uint32_t g_Wt2h[(D2 / 2) * D2];    // [k2][n] half2-packed weights (B)
__device__ int    g_src[EM];
__device__ int    g_dst[EM];
__device__ int    g_adj[2][EM];
__device__ int    g_cnt[2][NM];
__device__ int    g_rowptr[2][NM];
__device__ int    g_cursor[2][NM];
__device__ float  g_inv[2][NM];
__device__ int    g_part[2][64];
__device__ int    g_ready[2][64];             // publish flags for fused scan
__device__ int    g_flag32;                   // static-init 0; reset by scan each pass

// ------ setup: zero counts + feature->fp16 + int32/int64 detection --------
__global__ void initA_kernel(const float* __restrict__ feat,
                             const unsigned* __restrict__ edges32,
                             int n, int nfeat2, int E) {
    int i = blockIdx.x * blockDim.x + threadIdx.x;
    if (i < n) { g_cnt[0][i] = 0; g_cnt[1][i] = 0; }
    if (i < nfeat2) {
        float2 f = ((const float2*)feat)[i];
        ((__half2*)g_feath)[i] = __floats2half2_rn(f.x, f.y);
    }
    // detection: if edges are int64 (values < 50000) every odd word is 0.
    unsigned hiw = (i < E) ? edges32[2 * i + 1] : 0u;
    if (__any_sync(__activemask(), hiw != 0u) && (threadIdx.x & 31) == 0 && hiw != 0u)
        g_flag32 = 1;   // benign race: all writers store 1
}

// convert + count, 4 edges/thread, NO-RETURN atomics (REDG); resets scan flags.
__global__ void convert_count_kernel(const void* __restrict__ e, int E) {
    int gt = blockIdx.x * blockDim.x + threadIdx.x;
    if (gt < 128) ((int*)g_ready)[gt] = 0;
    int base = gt * 4;
    if (base >= E) return;
    int cnt = min(4, E - base);
    int s[4], d[4];
    if (g_flag32) {
        const int* p = (const int*)e;
        for (int j = 0; j < cnt; j++) { s[j] = p[base + j]; d[j] = p[E + base + j]; }
    } else {
        const long long* p = (const long long*)e;
        for (int j = 0; j < cnt; j++) { s[j] = (int)p[base + j]; d[j] = (int)p[E + base + j]; }
    }
    for (int j = 0; j < cnt; j++) { g_src[base + j] = s[j]; g_dst[base + j] = d[j]; }
    for (int j = 0; j < cnt; j++) atomicAdd(&g_cnt[0][d[j]], 1);
    for (int j = 0; j < cnt; j++) atomicAdd(&g_cnt[1][s[j]], 1);
}

// ---- fused single-pass scan: block scan + cross-block spin-prefix --------
// Grid (NB, 2) = 98 blocks of 1024 <= 148 SMs -> co-resident wave 1.
__global__ void scan_fused_kernel(const float* __restrict__ W, int n) {
    int flat = (blockIdx.y * NB + blockIdx.x) * 1024 + threadIdx.x;
    if (flat < (D2 / 2) * D2) {
        int k2 = flat / D2, j = flat % D2;
        int base = (j < ODIM) ? j * 512 + 2 * k2 : (j - ODIM) * 512 + 256 + 2 * k2;
        __half2 h = __floats2half2_rn(W[base], W[base + 1]);
        g_Wt2h[flat] = *(uint32_t*)&h;
    }
    if (flat == 0) g_flag32 = 0;      // reset for next replay

    int dir = blockIdx.y;
    int tid = threadIdx.x;
    int i = blockIdx.x * 1024 + tid;
    int v = (i < n) ? g_cnt[dir][i] : 0;
    int lane = tid & 31, w = tid >> 5;
    int x = v;
    #pragma unroll
    for (int o = 1; o < 32; o <<= 1) {
        int y = __shfl_up_sync(0xffffffffu, x, o);
        if (lane >= o) x += y;
    }
    __shared__ int ws[32];
    __shared__ int base_s;
    if (lane == 31) ws[w] = x;
    __syncthreads();
    if (w == 0) {
        int y = ws[lane];
        #pragma unroll
        for (int o = 1; o < 32; o <<= 1) {
            int z = __shfl_up_sync(0xffffffffu, y, o);
            if (lane >= o) y += z;
        }
        ws[lane] = y;
    }
    __syncthreads();
    int excl = x - v + (w ? ws[w - 1] : 0);

    if (tid == 0) {
        g_part[dir][blockIdx.x] = ws[31];
        __threadfence();
        atomicExch(&g_ready[dir][blockIdx.x], 1);
    }
    if (w == 0) {
        int acc = 0;
        for (int b = lane; b < (int)blockIdx.x; b += 32) {
            while (atomicAdd(&g_ready[dir][b], 0) == 0) { }
            acc += g_part[dir][b];
        }
        #pragma unroll
        for (int o = 16; o; o >>= 1) acc += __shfl_down_sync(0xffffffffu, acc, o);
        if (lane == 0) base_s = acc;
    }
    __syncthreads();
    if (i < n) {
        int r = excl + base_s;
        g_rowptr[dir][i] = r;
        g_cursor[dir][i] = r;
        g_inv[dir][i] = 1.0f / fmaxf((float)v, 1.0f);
    }
}

// ---- fill: 1 edge/thread; both cursor atomics issued before the stores ---
__global__ void fill_kernel(int E) {
    int i = blockIdx.x * blockDim.x + threadIdx.x;
    if (i >= E) return;
    int s = g_src[i], d = g_dst[i];
    int p = atomicAdd(&g_cursor[0][d], 1);
    int q = atomicAdd(&g_cursor[1][s], 1);
    g_adj[0][p] = s;
    g_adj[1][q] = d;
}

// ---------------- hop1: feat fp16 (D=64) -> h1 fp16 [N,128] ---------------
// 8-neighbor chunks + serial tail (byte-minimal, measured-best form).
__global__ void __launch_bounds__(256) hop1_kernel(__half* __restrict__ h1, int n) {
    int gid = blockIdx.x * blockDim.x + threadIdx.x;
    int node = gid >> 4;
    int lane = gid & 15;
    int dir = blockIdx.y;
    if (node >= n) return;
    int start = g_rowptr[dir][node];
    int deg   = g_cnt[dir][node];
    const int* adj = g_adj[dir] + start;
    float acc[4] = {};
    int t = 0;
    for (; t + 8 <= deg; t += 8) {
        int u[8];
        #pragma unroll
        for (int j = 0; j < 8; j++) u[j] = __ldg(&adj[t + j]);
        uint2 rs[8];
        #pragma unroll
        for (int j = 0; j < 8; j++)
            rs[j] = __ldg((const uint2*)(g_feath + (size_t)u[j] * D0) + lane);
        #pragma unroll
        for (int p = 0; p < 4; p++) {
            const __half2* a = (const __half2*)&rs[2 * p];
            const __half2* b = (const __half2*)&rs[2 * p + 1];
            __half2 s0 = __hadd2(a[0], b[0]);
            __half2 s1 = __hadd2(a[1], b[1]);
            float2 f0 = __half22float2(s0);
            float2 f1 = __half22float2(s1);
            acc[0] += f0.x; acc[1] += f0.y; acc[2] += f1.x; acc[3] += f1.y;
        }
    }
    for (; t < deg; t++) {
        int u = __ldg(&adj[t]);
        uint2 r = __ldg((const uint2*)(g_feath + (size_t)u * D0) + lane);
        float2 f0 = __half22float2(*(const __half2*)&r.x);
        float2 f1 = __half22float2(*(const __half2*)&r.y);
        acc[0] += f0.x; acc[1] += f0.y; acc[2] += f1.x; acc[3] += f1.y;
    }
    float w = g_inv[dir][node];
    __half2* out = (__half2*)(h1 + (size_t)node * D1 + dir * D0 + lane * 4);
    out[0] = __floats2half2_rn(acc[0] * w, acc[1] * w);
    out[1] = __floats2half2_rn(acc[2] * w, acc[3] * w);
}

// ---------------- hop2: h1 fp16 (D=128) -> h2 fp16 [N,256] ----------------
__global__ void __launch_bounds__(256) hop2_kernel(
    const __half* __restrict__ h1, __half* __restrict__ h2, int n)
{
    int gid = blockIdx.x * blockDim.x + threadIdx.x;
    int node = gid >> 4;
    int lane = gid & 15;
    int dir = blockIdx.y;
    if (node >= n) return;
    int start = g_rowptr[dir][node];
    int deg   = g_cnt[dir][node];
    const int* adj = g_adj[dir] + start;
    float acc[8] = {};
    int t = 0;
    for (; t + 8 <= deg; t += 8) {
        int u[8];
        #pragma unroll
        for (int j = 0; j < 8; j++) u[j] = __ldg(&adj[t + j]);
        uint4 rs[8];
        #pragma unroll
        for (int j = 0; j < 8; j++)
            rs[j] = __ldg((const uint4*)(h1 + (size_t)u[j] * D1) + lane);
        #pragma unroll
        for (int p = 0; p < 4; p++) {
            const __half2* a = (const __half2*)&rs[2 * p];
            const __half2* b = (const __half2*)&rs[2 * p + 1];
            #pragma unroll
            for (int j = 0; j < 4; j++) {
                __half2 s = __hadd2(a[j], b[j]);
                float2 f = __half22float2(s);
                acc[2 * j]     += f.x;
                acc[2 * j + 1] += f.y;
            }
        }
    }
    for (; t < deg; t++) {
        int u = __ldg(&adj[t]);
        uint4 r = __ldg((const uint4*)(h1 + (size_t)u * D1) + lane);
        const __half2* h = (const __half2*)&r;
        #pragma unroll
        for (int j = 0; j < 4; j++) {
            float2 f = __half22float2(h[j]);
            acc[2 * j]     += f.x;
            acc[2 * j + 1] += f.y;
        }
    }
    float w = g_inv[dir][node];
    __half2 o[4];
    #pragma unroll
    for (int j = 0; j < 4; j++)
        o[j] = __floats2half2_rn(acc[2 * j] * w, acc[2 * j + 1] * w);
    *(uint4*)(h2 + (size_t)node * D2 + dir * D1 + lane * 8) = *(uint4*)o;
}

// ---------------- fp16 GEMM, double-buffered smem (1 sync / k-tile) -------
__device__ __forceinline__ void mma_f16(float* c, const uint32_t* a,
                                        uint32_t b0, uint32_t b1) {
    asm volatile(
        "mma.sync.aligned.m16n8k16.row.col.f32.f16.f16.f32 "
        "{%0,%1,%2,%3}, {%4,%5,%6,%7}, {%8,%9}, {%0,%1,%2,%3};"
        : "+f"(c[0]), "+f"(c[1]), "+f"(c[2]), "+f"(c[3])
        : "r"(a[0]), "r"(a[1]), "r"(a[2]), "r"(a[3]), "r"(b0), "r"(b1));
}

__global__ void __launch_bounds__(256, 2) gemm_f16_kernel(
    const __half* __restrict__ A, __half* __restrict__ C, int N)
{
    __shared__ uint32_t As[2][128][20];
    __shared__ uint32_t Bs[2][16][136];
    int tid = threadIdx.x;
    int warp = tid >> 5, lane = tid & 31;
    int warpRow = warp >> 1;
    int warpCol = warp & 1;
    int g = lane >> 2, q = lane & 3;
    int blockRow = blockIdx.x * 128;
    int blockCol = blockIdx.y * 128;
    float c[2][8][4] = {};

    int arow = tid >> 2;
    int ac4  = tid & 3;
    int bk2  = tid >> 5;
    int bn4  = tid & 31;

    const uint4* Ag = (const uint4*)A;
    const uint4* Bg = (const uint4*)g_Wt2h;
    uint4 bufA[2], bufB[2];
    const uint4 zero4 = make_uint4(0u, 0u, 0u, 0u);

    #pragma unroll
    for (int i = 0; i < 2; i++) {
        int row = blockRow + arow + i * 64;
        bufA[i] = (row < N) ? __ldg(Ag + (size_t)row * 32 + ac4) : zero4;
        bufB[i] = __ldg(Bg + (size_t)(bk2 + i * 8) * 64 + (blockCol >> 2) + bn4);
    }
    #pragma unroll
    for (int i = 0; i < 2; i++) {
        *(uint4*)&As[0][arow + i * 64][ac4 * 4] = bufA[i];
        *(uint4*)&Bs[0][bk2 + i * 8][bn4 * 4] = bufB[i];
    }
    __syncthreads();

    for (int kt = 0; kt < 8; kt++) {
        int cur = kt & 1;
        if (kt < 7) {
            #pragma unroll
            for (int i = 0; i < 2; i++) {
                int row = blockRow + arow + i * 64;
                bufA[i] = (row < N) ? __ldg(Ag + (size_t)row * 32 + (kt + 1) * 4 + ac4) : zero4;
                bufB[i] = __ldg(Bg + (size_t)((kt + 1) * 16 + bk2 + i * 8) * 64 + (blockCol >> 2) + bn4);
            }
        }
        #pragma unroll
        for (int ks = 0; ks < 2; ks++) {
            int kb = ks * 8;
            uint32_t a[2][4];
            #pragma unroll
            for (int mt = 0; mt < 2; mt++) {
                int rb = warpRow * 32 + mt * 16;
                a[mt][0] = As[cur][rb + g    ][kb + q    ];
                a[mt][1] = As[cur][rb + g + 8][kb + q    ];
                a[mt][2] = As[cur][rb + g    ][kb + q + 4];
                a[mt][3] = As[cur][rb + g + 8][kb + q + 4];
            }
            #pragma unroll
            for (int nt = 0; nt < 8; nt++) {
                int cb = warpCol * 64 + nt * 8 + g;
                uint32_t b0 = Bs[cur][kb + q    ][cb];
                uint32_t b1 = Bs[cur][kb + q + 4][cb];
                mma_f16(c[0][nt], a[0], b0, b1);
                mma_f16(c[1][nt], a[1], b0, b1);
            }
        }
        if (kt < 7) {
            #pragma unroll
            for (int i = 0; i < 2; i++) {
                *(uint4*)&As[1 - cur][arow + i * 64][ac4 * 4] = bufA[i];
                *(uint4*)&Bs[1 - cur][bk2 + i * 8][bn4 * 4] = bufB[i];
            }
            __syncthreads();
        }
    }

    #pragma unroll
    for (int mt = 0; mt < 2; mt++)
        #pragma unroll
        for (int nt = 0; nt < 8; nt++) {
            int col = blockCol + warpCol * 64 + nt * 8 + q * 2;
            int r0 = blockRow + warpRow * 32 + mt * 16 + g;
            if (r0 < N)
                *(__half2*)(C + (size_t)r0 * D2 + col) =
                    __floats2half2_rn(c[mt][nt][0], c[mt][nt][1]);
            int r1 = r0 + 8;
            if (r1 < N)
                *(__half2*)(C + (size_t)r1 * D2 + col) =
                    __floats2half2_rn(c[mt][nt][2], c[mt][nt][3]);
        }
}

// ---------------- fused hop3: aggregate P fp16, scale, bias ---------------
__global__ void __launch_bounds__(256) hop3_kernel(
    const __half* __restrict__ P, const float* __restrict__ bias,
    float* __restrict__ out, int n)
{
    int node = blockIdx.x * 8 + (threadIdx.x >> 5);
    int lane = threadIdx.x & 31;
    if (node >= n) return;
    float aI[4] = {}, aO[4] = {};
    #pragma unroll
    for (int dir = 0; dir < 2; dir++) {
        float* acc = dir ? aO : aI;
        int off = dir ? ODIM : 0;
        int start = g_rowptr[dir][node];
        int deg   = g_cnt[dir][node];
        const int* adj = g_adj[dir] + start;
        int t = 0;
        for (; t + 8 <= deg; t += 8) {
            int u[8];
            #pragma unroll
            for (int j = 0; j < 8; j++) u[j] = __ldg(&adj[t + j]);
            uint2 rs[8];
            #pragma unroll
            for (int j = 0; j < 8; j++)
                rs[j] = __ldg((const uint2*)(P + (size_t)u[j] * D2 + off) + lane);
            #pragma unroll
            for (int p = 0; p < 4; p++) {
                const __half2* a = (const __half2*)&rs[2 * p];
                const __half2* b = (const __half2*)&rs[2 * p + 1];
                __half2 s0 = __hadd2(a[0], b[0]);
                __half2 s1 = __hadd2(a[1], b[1]);
                float2 f0 = __half22float2(s0);
                float2 f1 = __half22float2(s1);
                acc[0] += f0.x; acc[1] += f0.y; acc[2] += f1.x; acc[3] += f1.y;
            }
        }
        for (; t < deg; t++) {
            int u = __ldg(&adj[t]);
            uint2 r = __ldg((const uint2*)(P + (size_t)u * D2 + off) + lane);
            float2 f0 = __half22float2(*(const __half2*)&r.x);
            float2 f1 = __half22float2(*(const __half2*)&r.y);
            acc[0] += f0.x; acc[1] += f0.y; acc[2] += f1.x; acc[3] += f1.y;
        }
    }
    float wi = g_inv[0][node], wo = g_inv[1][node];
    float4 b = __ldg((const float4*)bias + lane);
    float4 r;
    r.x = aI[0] * wi + aO[0] * wo + b.x;
    r.y = aI[1] * wi + aO[1] * wo + b.y;
    r.z = aI[2] * wi + aO[2] * wo + b.z;
    r.w = aI[3] * wi + aO[3] * wo + b.w;
    ((float4*)(out + (size_t)node * ODIM))[lane] = r;
}

// ---------------- launch ----------------------------------------------------
extern "C" void kernel_launch(void* const* d_in, const int* in_sizes, int n_in,
                              void* d_out, int out_size)
{
    const float* feat  = (const float*)d_in[0];
    const void*  edges = d_in[1];
    const float* W     = (const float*)d_in[2];
    const float* bias  = (const float*)d_in[3];
    float* out = (float*)d_out;

    int N = in_sizes[0] / D0;     // 50000
    int E = in_sizes[1] / 2;      // 800000

    __half *h1, *h2, *P;
    cudaGetSymbolAddress((void**)&h1, g_h1h);
    cudaGetSymbolAddress((void**)&h2, g_h2h);
    cudaGetSymbolAddress((void**)&P,  g_Ph);

    const int T = 256;
    int nfeat2 = N * D0 / 2;
    initA_kernel<<<(nfeat2 + T - 1) / T, T>>>(feat, (const unsigned*)edges, N, nfeat2, E);
    {
        int threads = (E + 3) / 4;
        convert_count_kernel<<<(threads + T - 1) / T, T>>>(edges, E);
    }
    {
        dim3 sgrid(NB, 2);
        scan_fused_kernel<<<sgrid, 1024>>>(W, N);
    }
    fill_kernel<<<(E + T - 1) / T, T>>>(E);
    {
        unsigned total = (unsigned)N * 16;
        dim3 g((total + T - 1) / T, 2);
        hop1_kernel<<<g, T>>>(h1, N);
        hop2_kernel<<<g, T>>>(h1, h2, N);
    }
    {
        dim3 g((N + 127) / 128, 2);
        gemm_f16_kernel<<<g, T>>>(h2, P, N);
    }
    hop3_kernel<<<(N + 7) / 8, T>>>(P, bias, out, N);
}